// round 15
// baseline (speedup 1.0000x reference)
#include <cuda_runtime.h>
#include <cuda_fp16.h>
#include <cstdint>
#include <cstddef>

constexpr int cB=256, cT=128, cOBS=512, cE=1024, cH=1024, cA=64;
constexpr int cBT=cB*cT, cG=4*cH;

constexpr size_t OFF_LOGITS=0;
constexpr size_t OFF_VAL = OFF_LOGITS + (size_t)cBT*cA;
constexpr size_t OFF_OBS = OFF_VAL + (size_t)cBT;
constexpr size_t OFF_REW = OFF_OBS + (size_t)cBT*cOBS;
constexpr size_t OFF_HT  = OFF_REW + (size_t)cBT;
constexpr size_t OFF_CT  = OFF_HT + (size_t)cB*cH;

typedef __half f16;
// activations
__device__ f16 g_obs_h[(size_t)cBT*cOBS];
__device__ f16 g_e1h[(size_t)cBT*cE];
__device__ f16 g_e2h[(size_t)cBT*cE];
__device__ f16 g_xh[(size_t)cBT*cH];
__device__ f16 g_hh0[(size_t)cB*cH], g_hh1[(size_t)cB*cH];
__device__ f16 g_gx[(size_t)cBT*cG];       // [T,B,4H] f16
__device__ float g_hseq[(size_t)cBT*cH];   // [B,T,H] fp32
__device__ float g_c[(size_t)cB*cH];
// weights ([N,K])
__device__ f16 g_w1[(size_t)cE*cOBS];
__device__ f16 g_w2[(size_t)cE*cE];
__device__ f16 g_whd[(size_t)(cA+cOBS)*cH];   // combined [Wa ; Wobs]
__device__ f16 g_wih[(size_t)cG*cE];
__device__ f16 g_whh[(size_t)cG*cH];

__device__ __forceinline__ uint32_t smem_u32(const void* p){
    uint32_t a; asm("{ .reg .u64 t; cvta.to.shared.u64 t, %1; cvt.u32.u64 %0, t; }":"=r"(a):"l"(p)); return a;
}
__device__ __forceinline__ void cpasync16(uint32_t d, const void* g){
    asm volatile("cp.async.cg.shared.global [%0], [%1], 16;"::"r"(d),"l"(g):"memory");
}
#define CP_COMMIT() asm volatile("cp.async.commit_group;" ::: "memory")
#define CP_WAIT1()  asm volatile("cp.async.wait_group 1;" ::: "memory")
__device__ __forceinline__ void ldsm4(uint32_t (&r)[4], uint32_t a){
    asm volatile("ldmatrix.sync.aligned.m8n8.x4.shared.b16 {%0,%1,%2,%3}, [%4];"
        : "=r"(r[0]),"=r"(r[1]),"=r"(r[2]),"=r"(r[3]) : "r"(a));
}
__device__ __forceinline__ void mma16816(float (&d)[4], const uint32_t (&a)[4],
                                         uint32_t b0, uint32_t b1){
    asm volatile("mma.sync.aligned.m16n8k16.row.col.f32.f16.f16.f32 "
        "{%0,%1,%2,%3}, {%4,%5,%6,%7}, {%8,%9}, {%0,%1,%2,%3};"
        : "+f"(d[0]),"+f"(d[1]),"+f"(d[2]),"+f"(d[3])
        : "r"(a[0]),"r"(a[1]),"r"(a[2]),"r"(a[3]),"r"(b0),"r"(b1));
}
__device__ __forceinline__ float sigm_(float x){ return 1.f/(1.f+expf(-x)); }

// ---------------------------------------------------------------------------
// fp16 tensor GEMM, BK=64, 3-stage cp.async pipeline, single segment Ah*Bh.
// EPI: 0=+bias->f32 ; 4=silu(+bias)->single f16 ;
//      5=+bias+bias2, row swizzle r->(r%Tsw)*Bsw+r/Tsw -> f16 (gx) ;
//      6=split heads: col<64 -> Cf[row*64+col]+bias ; else Cf2[row*512+col-64]+bias2
// ---------------------------------------------------------------------------
template<int BN, int EPI>
__global__ void __launch_bounds__(256, 2)
tgemm_k(const f16* __restrict__ Ah, const f16* __restrict__ Bh,
        float* __restrict__ Cf, float* __restrict__ Cf2, f16* __restrict__ Ch,
        const float* __restrict__ bias, const float* __restrict__ bias2,
        int Ngl, int K, int Tsw, int Bsw)
{
    constexpr int BM=128, BK=64, STR=72, S=3;
    constexpr int ABYTES = BM*STR*2, BBYTES = BN*STR*2;
    constexpr int BNW = BN/2, NP = BNW/16, NT8 = BNW/8;
    constexpr int APT = (BM*(BK/8))/256, BPT = (BN*(BK/8))/256;

    extern __shared__ char smem_[];
    const uint32_t sA = smem_u32(smem_);
    const uint32_t sB = sA + S*ABYTES;

    const int tid = threadIdx.x, lane = tid & 31, wid = tid >> 5;
    const int wm = wid & 3, wn = wid >> 2;
    const int m0 = blockIdx.y * BM, n0 = blockIdx.x * BN;

    float acc[2][NT8][4];
#pragma unroll
    for (int i = 0; i < 2; i++)
#pragma unroll
        for (int j = 0; j < NT8; j++)
#pragma unroll
            for (int q = 0; q < 4; q++) acc[i][j][q] = 0.f;

    const int NT = K / BK;

    auto load_tile = [&](int c, int buf){
        const int kk = c * BK;
#pragma unroll
        for (int p = 0; p < APT; p++) {
            int i = p*256 + tid, r = i >> 3, c8 = i & 7;
            cpasync16(sA + buf*ABYTES + (r*STR + c8*8)*2,
                      Ah + (size_t)(m0 + r)*K + kk + c8*8);
        }
#pragma unroll
        for (int p = 0; p < BPT; p++) {
            int i = p*256 + tid, r = i >> 3, c8 = i & 7;
            cpasync16(sB + buf*BBYTES + (r*STR + c8*8)*2,
                      Bh + (size_t)(n0 + r)*K + kk + c8*8);
        }
        CP_COMMIT();
    };

    const int aRow = wm*32 + (lane & 15);
    const int aCol = (lane >> 4) * 8;
    const int bRow = wn*BNW + (lane & 7) + ((lane >> 4) & 1) * 8;
    const int bCol = ((lane >> 3) & 1) * 8;

    load_tile(0, 0);
    load_tile(1, 1);
    for (int c = 0; c < NT; ++c) {
        const int buf = c % S;
        CP_WAIT1();
        __syncthreads();
        if (c + 2 < NT) load_tile(c + 2, (c + 2) % S); else CP_COMMIT();

#pragma unroll
        for (int kk2 = 0; kk2 < BK; kk2 += 16) {
            uint32_t a[2][4];
#pragma unroll
            for (int mi = 0; mi < 2; mi++)
                ldsm4(a[mi], sA + buf*ABYTES + ((aRow + mi*16)*STR + kk2 + aCol)*2);
            uint32_t b[NP][4];
#pragma unroll
            for (int np = 0; np < NP; np++)
                ldsm4(b[np], sB + buf*BBYTES + ((bRow + np*16)*STR + kk2 + bCol)*2);
#pragma unroll
            for (int mi = 0; mi < 2; mi++)
#pragma unroll
                for (int np = 0; np < NP; np++) {
                    mma16816(acc[mi][2*np],   a[mi], b[np][0], b[np][1]);
                    mma16816(acc[mi][2*np+1], a[mi], b[np][2], b[np][3]);
                }
        }
    }

    const int g = lane >> 2, t = lane & 3;
    auto emit = [&](int row, int col, float v0, float v1){
        if constexpr (EPI == 4) {
            v0 += bias[col]; v1 += bias[col+1];
            v0 = v0 / (1.f + expf(-v0)); v1 = v1 / (1.f + expf(-v1));
            *reinterpret_cast<__half2*>(Ch + (size_t)row*Ngl + col) =
                __halves2half2(__float2half(v0), __float2half(v1));
        } else if constexpr (EPI == 0) {
            float2 o; o.x = v0 + bias[col]; o.y = v1 + bias[col+1];
            *reinterpret_cast<float2*>(Cf + (size_t)row*Ngl + col) = o;
        } else if constexpr (EPI == 5) {
            size_t orow = (size_t)((row % Tsw) * Bsw + row / Tsw);
            float o0 = v0 + bias[col] + bias2[col];
            float o1 = v1 + bias[col+1] + bias2[col+1];
            *reinterpret_cast<__half2*>(Ch + orow*(size_t)Ngl + col) =
                __halves2half2(__float2half(o0), __float2half(o1));
        } else { // EPI == 6
            if (col < cA) {
                float2 o; o.x = v0 + bias[col]; o.y = v1 + bias[col+1];
                *reinterpret_cast<float2*>(Cf + (size_t)row*cA + col) = o;
            } else {
                int c2 = col - cA;
                float2 o; o.x = v0 + bias2[c2]; o.y = v1 + bias2[c2+1];
                *reinterpret_cast<float2*>(Cf2 + (size_t)row*cOBS + c2) = o;
            }
        }
    };
#pragma unroll
    for (int mi = 0; mi < 2; mi++)
#pragma unroll
        for (int ni = 0; ni < NT8; ni++) {
            int row = m0 + wm*32 + mi*16 + g;
            int col = n0 + wn*BNW + ni*8 + 2*t;
            emit(row,     col, acc[mi][ni][0], acc[mi][ni][1]);
            emit(row + 8, col, acc[mi][ni][2], acc[mi][ni][3]);
        }
}

// ---------------------------------------------------------------------------
// Fused LSTM step with PDL: trigger successor launch at entry; block on
// predecessor completion (grid dependency) before any loads/stores.
// Single-segment fp16 gates GEMM (128x64 tile: 4 gates x 16 j) + cell update.
// grid (cH/16, cB/128). Final step writes hT/cT directly to output.
// ---------------------------------------------------------------------------
__global__ void __launch_bounds__(256)
scan_step_k(const f16* __restrict__ hih, const f16* __restrict__ Bw,
            const f16* __restrict__ gxt, const float* __restrict__ cin,
            float* __restrict__ cout, f16* __restrict__ hoh,
            float* __restrict__ hseq, int t,
            float* __restrict__ outh, float* __restrict__ outc)
{
    constexpr int BM=128, BN=64, BK=64, STR=72, S=3, K=cH;
    constexpr int ABYTES = BM*STR*2, BBYTES = BN*STR*2;
    constexpr int BNW=32, NP=2, NT8=4;

    // PDL: allow the next scan step to launch immediately; then wait for the
    // previous step's memory (h, c) to be visible before touching anything.
    cudaTriggerProgrammaticLaunchCompletion();
    cudaGridDependencySynchronize();

    extern __shared__ char smem_[];
    const uint32_t sA = smem_u32(smem_);
    const uint32_t sB = sA + S*ABYTES;
    float* sg = reinterpret_cast<float*>(smem_);   // epilogue alias: [128][66]

    const int tid = threadIdx.x, lane = tid & 31, wid = tid >> 5;
    const int wm = wid & 3, wn = wid >> 2;
    const int m0 = blockIdx.y * BM, j0 = blockIdx.x * 16;

    float acc[2][NT8][4];
#pragma unroll
    for (int i = 0; i < 2; i++)
#pragma unroll
        for (int j = 0; j < NT8; j++)
#pragma unroll
            for (int q = 0; q < 4; q++) acc[i][j][q] = 0.f;

    const int NT = K / BK;   // 16

    auto load_tile = [&](int c, int buf){
        const int kk = c * BK;
#pragma unroll
        for (int p = 0; p < 4; p++) {
            int i = p*256 + tid, r = i >> 3, c8 = i & 7;
            cpasync16(sA + buf*ABYTES + (r*STR + c8*8)*2,
                      hih + (size_t)(m0 + r)*K + kk + c8*8);
        }
#pragma unroll
        for (int p = 0; p < 2; p++) {
            int i = p*256 + tid, r = i >> 3, c8 = i & 7;
            int grow = (r >> 4)*cH + j0 + (r & 15);
            cpasync16(sB + buf*BBYTES + (r*STR + c8*8)*2,
                      Bw + (size_t)grow*K + kk + c8*8);
        }
        CP_COMMIT();
    };

    const int aRow = wm*32 + (lane & 15);
    const int aCol = (lane >> 4) * 8;
    const int bRow = wn*BNW + (lane & 7) + ((lane >> 4) & 1) * 8;
    const int bCol = ((lane >> 3) & 1) * 8;

    load_tile(0, 0);
    load_tile(1, 1);
    for (int c = 0; c < NT; ++c) {
        const int buf = c % S;
        CP_WAIT1();
        __syncthreads();
        if (c + 2 < NT) load_tile(c + 2, (c + 2) % S); else CP_COMMIT();
#pragma unroll
        for (int kk2 = 0; kk2 < BK; kk2 += 16) {
            uint32_t a[2][4];
#pragma unroll
            for (int mi = 0; mi < 2; mi++)
                ldsm4(a[mi], sA + buf*ABYTES + ((aRow + mi*16)*STR + kk2 + aCol)*2);
            uint32_t b[NP][4];
#pragma unroll
            for (int np = 0; np < NP; np++)
                ldsm4(b[np], sB + buf*BBYTES + ((bRow + np*16)*STR + kk2 + bCol)*2);
#pragma unroll
            for (int mi = 0; mi < 2; mi++)
#pragma unroll
                for (int np = 0; np < NP; np++) {
                    mma16816(acc[mi][2*np],   a[mi], b[np][0], b[np][1]);
                    mma16816(acc[mi][2*np+1], a[mi], b[np][2], b[np][3]);
                }
        }
    }
    __syncthreads();   // all ldsm done before smem alias reuse

    const int g_ = lane >> 2, t_ = lane & 3;
#pragma unroll
    for (int mi = 0; mi < 2; mi++)
#pragma unroll
        for (int ni = 0; ni < NT8; ni++) {
            int rowl = wm*32 + mi*16 + g_;
            int col  = wn*BNW + ni*8 + 2*t_;
            int gate = col >> 4, jj = col & 15;
#pragma unroll
            for (int half = 0; half < 2; half++) {
                int rr = rowl + half*8;
                __half2 gxh = *reinterpret_cast<const __half2*>(
                    gxt + (size_t)(m0+rr)*cG + gate*cH + j0 + jj);
                float2 gxv = __half22float2(gxh);
                sg[rr*66 + col]     = acc[mi][ni][2*half]   + gxv.x;
                sg[rr*66 + col + 1] = acc[mi][ni][2*half+1] + gxv.y;
            }
        }
    __syncthreads();

    const bool last = (t == cT - 1);
#pragma unroll
    for (int k = 0; k < 8; k++) {
        int idx = tid + k*256;
        int row = idx & 127, jj = idx >> 7;
        float i_ = sigm_(sg[row*66 + jj]);
        float f_ = sigm_(sg[row*66 + 16 + jj]);
        float g2 = tanhf(sg[row*66 + 32 + jj]);
        float o_ = sigm_(sg[row*66 + 48 + jj]);
        size_t ci = (size_t)(m0+row)*cH + j0 + jj;
        float cc = f_ * cin[ci] + i_ * g2;
        float hv = o_ * tanhf(cc);
        hseq[((size_t)(m0+row)*cT + t)*cH + j0 + jj] = hv;
        if (last) {
            outh[ci] = hv;
            outc[ci] = cc;
        } else {
            cout[ci] = cc;
            hoh[ci] = __float2half(hv);
        }
    }
}

// ---------------- conversion / pointwise kernels ----------------
__global__ void conv_h_k(const float* __restrict__ in, f16* __restrict__ o, size_t n4)
{
    size_t i = (size_t)blockIdx.x*blockDim.x + threadIdx.x;
    if (i >= n4) return;
    float4 v = reinterpret_cast<const float4*>(in)[i];
    reinterpret_cast<__half2*>(o)[i*2]   = __halves2half2(__float2half(v.x), __float2half(v.y));
    reinterpret_cast<__half2*>(o)[i*2+1] = __halves2half2(__float2half(v.z), __float2half(v.w));
}
__global__ void convT_k(const float* __restrict__ W, f16* __restrict__ o, int K, int N)
{
    __shared__ float t[32][33];
    int tx = threadIdx.x, ty = threadIdx.y;
#pragma unroll
    for (int r = 0; r < 4; r++)
        t[ty+8*r][tx] = W[(size_t)(blockIdx.y*32 + ty + 8*r)*N + blockIdx.x*32 + tx];
    __syncthreads();
#pragma unroll
    for (int r = 0; r < 4; r++) {
        int n = blockIdx.x*32 + ty + 8*r, k = blockIdx.y*32 + tx;
        o[(size_t)n*K + k] = __float2half(t[tx][ty+8*r]);
    }
}
// Fused layernorm + xh(f16) output + values/rew GEMV (fp32-exact from y regs)
__global__ void ln_head_k(const float* __restrict__ in, f16* __restrict__ oh,
                          const float* __restrict__ gw, const float* __restrict__ bw,
                          const float* __restrict__ wc, const float* __restrict__ wr,
                          const float* __restrict__ bc, const float* __restrict__ br,
                          float* __restrict__ outv, float* __restrict__ outr)
{
    const int row = blockIdx.x;
    const float* x = in + (size_t)row*cH;
    const int i = threadIdx.x*4;
    float4 v = *reinterpret_cast<const float4*>(x + i);
    float s  = v.x + v.y + v.z + v.w;
    float ss = v.x*v.x + v.y*v.y + v.z*v.z + v.w*v.w;

    __shared__ float red[64];
    int w = threadIdx.x/32, lane = threadIdx.x%32;
    for (int o = 16; o > 0; o >>= 1) { s += __shfl_xor_sync(~0u,s,o); ss += __shfl_xor_sync(~0u,ss,o); }
    if (lane == 0) { red[w] = s; red[32+w] = ss; }
    __syncthreads();
    if (threadIdx.x < 32) {
        float a = (threadIdx.x < 8) ? red[threadIdx.x] : 0.f;
        float b = (threadIdx.x < 8) ? red[32+threadIdx.x] : 0.f;
        for (int o = 4; o > 0; o >>= 1) { a += __shfl_xor_sync(~0u,a,o); b += __shfl_xor_sync(~0u,b,o); }
        if (threadIdx.x == 0) { red[0] = a; red[1] = b; }
    }
    __syncthreads();
    float mu = red[0]/cH, var = red[1]/cH - mu*mu, rstd = rsqrtf(var + 1e-5f);

    float4 gv = *reinterpret_cast<const float4*>(gw + i);
    float4 bv = *reinterpret_cast<const float4*>(bw + i);
    float y0 = (v.x-mu)*rstd*gv.x + bv.x;
    float y1 = (v.y-mu)*rstd*gv.y + bv.y;
    float y2 = (v.z-mu)*rstd*gv.z + bv.z;
    float y3 = (v.w-mu)*rstd*gv.w + bv.w;

    __half2 h01 = __halves2half2(__float2half(y0), __float2half(y1));
    __half2 h23 = __halves2half2(__float2half(y2), __float2half(y3));
    *reinterpret_cast<uint2*>(oh + (size_t)row*cH + i) =
        make_uint2(*reinterpret_cast<uint32_t*>(&h01), *reinterpret_cast<uint32_t*>(&h23));

    float4 cv = *reinterpret_cast<const float4*>(wc + i);
    float4 rv = *reinterpret_cast<const float4*>(wr + i);
    float sc = y0*cv.x + y1*cv.y + y2*cv.z + y3*cv.w;
    float sr = y0*rv.x + y1*rv.y + y2*rv.z + y3*rv.w;
    __syncthreads();   // red reuse
    for (int o = 16; o > 0; o >>= 1) { sc += __shfl_xor_sync(~0u,sc,o); sr += __shfl_xor_sync(~0u,sr,o); }
    if (lane == 0) { red[w] = sc; red[32+w] = sr; }
    __syncthreads();
    if (threadIdx.x == 0) {
        float a = 0.f, b = 0.f;
#pragma unroll
        for (int q = 0; q < 8; q++) { a += red[q]; b += red[32+q]; }
        outv[row] = a + bc[0];
        outr[row] = b + br[0];
    }
}

// ---------------------------------------------------------------------------
extern "C" void kernel_launch(void* const* d_in, const int* in_sizes, int n_in,
                              void* d_out, int out_size)
{
    const float* obs  = (const float*)d_in[0];
    const float* h0   = (const float*)d_in[1];
    const float* c0   = (const float*)d_in[2];
    const float* W1   = (const float*)d_in[3];
    const float* b1   = (const float*)d_in[4];
    const float* W2   = (const float*)d_in[5];
    const float* b2   = (const float*)d_in[6];
    const float* w_ih = (const float*)d_in[7];
    const float* w_hh = (const float*)d_in[8];
    const float* b_ih = (const float*)d_in[9];
    const float* b_hh = (const float*)d_in[10];
    const float* ln_g = (const float*)d_in[11];
    const float* ln_b = (const float*)d_in[12];
    const float* Wa   = (const float*)d_in[13];
    const float* ba   = (const float*)d_in[14];
    const float* Wc   = (const float*)d_in[15];
    const float* bc   = (const float*)d_in[16];
    const float* Wobs = (const float*)d_in[17];
    const float* bobs = (const float*)d_in[18];
    const float* Wr   = (const float*)d_in[19];
    const float* br   = (const float*)d_in[20];
    float* out = (float*)d_out;

    f16 *obs_h,*e1h,*e2h,*xh,*hh0,*hh1,*gx;
    f16 *w1,*w2,*whd,*wih,*whh;
    float *hseq,*cbuf;
    cudaGetSymbolAddress((void**)&obs_h, g_obs_h);
    cudaGetSymbolAddress((void**)&e1h, g_e1h);
    cudaGetSymbolAddress((void**)&e2h, g_e2h);
    cudaGetSymbolAddress((void**)&xh, g_xh);
    cudaGetSymbolAddress((void**)&hh0, g_hh0); cudaGetSymbolAddress((void**)&hh1, g_hh1);
    cudaGetSymbolAddress((void**)&w1, g_w1);   cudaGetSymbolAddress((void**)&w2, g_w2);
    cudaGetSymbolAddress((void**)&whd, g_whd);
    cudaGetSymbolAddress((void**)&wih, g_wih); cudaGetSymbolAddress((void**)&whh, g_whh);
    cudaGetSymbolAddress((void**)&gx, g_gx);   cudaGetSymbolAddress((void**)&hseq, g_hseq);
    cudaGetSymbolAddress((void**)&cbuf, g_c);

    const int SM128 = 3*(128*72*2 + 128*72*2);   // 110592
    const int SM64  = 3*(128*72*2 + 64*72*2);    // 82944
    cudaFuncSetAttribute(tgemm_k<128,4>, cudaFuncAttributeMaxDynamicSharedMemorySize, SM128);
    cudaFuncSetAttribute(tgemm_k<128,5>, cudaFuncAttributeMaxDynamicSharedMemorySize, SM128);
    cudaFuncSetAttribute(tgemm_k<64,6>,  cudaFuncAttributeMaxDynamicSharedMemorySize, SM64);
    cudaFuncSetAttribute(scan_step_k,    cudaFuncAttributeMaxDynamicSharedMemorySize, SM64);

    // conversions (all single fp16)
    conv_h_k<<<((size_t)cBT*cOBS/4 + 255)/256, 256>>>(obs, obs_h, (size_t)cBT*cOBS/4);
    conv_h_k<<<((size_t)cB*cH/4 + 255)/256, 256>>>(h0, hh0, (size_t)cB*cH/4);
    conv_h_k<<<((size_t)cG*cE/4 + 255)/256, 256>>>(w_ih, wih, (size_t)cG*cE/4);
    conv_h_k<<<((size_t)cG*cH/4 + 255)/256, 256>>>(w_hh, whh, (size_t)cG*cH/4);
    { dim3 b(32,8);
      convT_k<<<dim3(cE/32, cOBS/32), b>>>(W1, w1, cOBS, cE);
      convT_k<<<dim3(cE/32, cE/32), b>>>(W2, w2, cE, cE);
      convT_k<<<dim3(cA/32, cH/32), b>>>(Wa, whd, cH, cA);
      convT_k<<<dim3(cOBS/32, cH/32), b>>>(Wobs, whd + (size_t)cA*cH, cH, cOBS); }

    // 1) enc1 = silu(obs @ W1 + b1)
    tgemm_k<128,4><<<dim3(cE/128, cBT/128), 256, SM128>>>(
        obs_h, w1, nullptr, nullptr, e1h, b1, nullptr, cE, cOBS, 0, 0);
    // 2) enc2 = silu(enc1 @ W2 + b2)
    tgemm_k<128,4><<<dim3(cE/128, cBT/128), 256, SM128>>>(
        e1h, w2, nullptr, nullptr, e2h, b2, nullptr, cE, cE, 0, 0);
    // 3) gx = enc2 @ w_ih^T + (b_ih + b_hh), stored [T,B,4H] f16
    tgemm_k<128,5><<<dim3(cG/128, cBT/128), 256, SM128>>>(
        e2h, wih, nullptr, nullptr, gx, b_ih, b_hh, cG, cE, cT, cB);
    // 4) fused scan with PDL chaining (per-step launches; last writes hT/cT)
    {
        cudaLaunchAttribute attrs[1];
        attrs[0].id = cudaLaunchAttributeProgrammaticStreamSerialization;
        attrs[0].val.programmaticStreamSerializationAllowed = 1;
        cudaLaunchConfig_t cfg = {};
        cfg.gridDim = dim3(cH/16, cB/128, 1);
        cfg.blockDim = dim3(256, 1, 1);
        cfg.dynamicSmemBytes = SM64;
        cfg.stream = 0;
        cfg.attrs = attrs;
        cfg.numAttrs = 1;
        for (int t = 0; t < cT; ++t) {
            const f16* hi = (t & 1) ? hh1 : hh0;
            f16* ho = (t & 1) ? hh0 : hh1;
            const f16* gxt = gx + (size_t)t*cB*cG;
            const float* cin = (t == 0) ? c0 : cbuf;
            float* outh = out + OFF_HT;
            float* outc = out + OFF_CT;
            cudaLaunchKernelEx(&cfg, scan_step_k,
                hi, whh, gxt, cin, cbuf, ho, hseq, t, outh, outc);
        }
    }
    // 5) fused layernorm + xh + values/rew
    ln_head_k<<<cBT, 256>>>(hseq, xh, ln_g, ln_b, Wc, Wr, bc, br,
                            out + OFF_VAL, out + OFF_REW);
    // 6+7) combined heads: [logits | obs_pred] = xh @ [Wa;Wobs]^T, N=576
    tgemm_k<64,6><<<dim3((cA+cOBS)/64, cBT/128), 256, SM64>>>(
        xh, whd, out + OFF_LOGITS, out + OFF_OBS, nullptr, ba, bobs, cA+cOBS, cH, 0, 0);
}

// round 16
// speedup vs baseline: 1.3572x; 1.3572x over previous
#include <cuda_runtime.h>
#include <cuda_fp16.h>
#include <cstdint>
#include <cstddef>

constexpr int cB=256, cT=128, cOBS=512, cE=1024, cH=1024, cA=64;
constexpr int cBT=cB*cT, cG=4*cH;

constexpr size_t OFF_LOGITS=0;
constexpr size_t OFF_VAL = OFF_LOGITS + (size_t)cBT*cA;
constexpr size_t OFF_OBS = OFF_VAL + (size_t)cBT;
constexpr size_t OFF_REW = OFF_OBS + (size_t)cBT*cOBS;
constexpr size_t OFF_HT  = OFF_REW + (size_t)cBT;
constexpr size_t OFF_CT  = OFF_HT + (size_t)cB*cH;

typedef __half f16;
// activations
__device__ f16 g_obs_h[(size_t)cBT*cOBS];
__device__ f16 g_e1h[(size_t)cBT*cE];
__device__ f16 g_e2h[(size_t)cBT*cE];
__device__ f16 g_xh[(size_t)cBT*cH];
__device__ f16 g_hh0[(size_t)cB*cH], g_hh1[(size_t)cB*cH];
__device__ f16 g_gx[(size_t)cBT*cG];       // [T,B,4H] f16
__device__ float g_hseq[(size_t)cBT*cH];   // [B,T,H] fp32
__device__ float g_c[(size_t)cB*cH];
// weights ([N,K])
__device__ f16 g_w1[(size_t)cE*cOBS];
__device__ f16 g_w2[(size_t)cE*cE];
__device__ f16 g_whd[(size_t)(cA+cOBS)*cH];   // combined [Wa ; Wobs]
__device__ f16 g_wih[(size_t)cG*cE];
__device__ f16 g_whh[(size_t)cG*cH];

__device__ __forceinline__ uint32_t smem_u32(const void* p){
    uint32_t a; asm("{ .reg .u64 t; cvta.to.shared.u64 t, %1; cvt.u32.u64 %0, t; }":"=r"(a):"l"(p)); return a;
}
__device__ __forceinline__ void cpasync16(uint32_t d, const void* g){
    asm volatile("cp.async.cg.shared.global [%0], [%1], 16;"::"r"(d),"l"(g):"memory");
}
#define CP_COMMIT() asm volatile("cp.async.commit_group;" ::: "memory")
#define CP_WAIT1()  asm volatile("cp.async.wait_group 1;" ::: "memory")
__device__ __forceinline__ void ldsm4(uint32_t (&r)[4], uint32_t a){
    asm volatile("ldmatrix.sync.aligned.m8n8.x4.shared.b16 {%0,%1,%2,%3}, [%4];"
        : "=r"(r[0]),"=r"(r[1]),"=r"(r[2]),"=r"(r[3]) : "r"(a));
}
__device__ __forceinline__ void mma16816(float (&d)[4], const uint32_t (&a)[4],
                                         uint32_t b0, uint32_t b1){
    asm volatile("mma.sync.aligned.m16n8k16.row.col.f32.f16.f16.f32 "
        "{%0,%1,%2,%3}, {%4,%5,%6,%7}, {%8,%9}, {%0,%1,%2,%3};"
        : "+f"(d[0]),"+f"(d[1]),"+f"(d[2]),"+f"(d[3])
        : "r"(a[0]),"r"(a[1]),"r"(a[2]),"r"(a[3]),"r"(b0),"r"(b1));
}
__device__ __forceinline__ float sigm_(float x){ return 1.f/(1.f+expf(-x)); }

// ---------------------------------------------------------------------------
// fp16 tensor GEMM, BK=64, 3-stage cp.async pipeline, single segment Ah*Bh.
// EPI: 0=+bias->f32 ; 4=silu(+bias)->single f16 ;
//      5=+bias+bias2, row swizzle r->(r%Tsw)*Bsw+r/Tsw -> f16 (gx) ;
//      6=split heads: col<64 -> Cf[row*64+col]+bias ; else Cf2[row*512+col-64]+bias2
// ---------------------------------------------------------------------------
template<int BN, int EPI>
__global__ void __launch_bounds__(256, 2)
tgemm_k(const f16* __restrict__ Ah, const f16* __restrict__ Bh,
        float* __restrict__ Cf, float* __restrict__ Cf2, f16* __restrict__ Ch,
        const float* __restrict__ bias, const float* __restrict__ bias2,
        int Ngl, int K, int Tsw, int Bsw)
{
    constexpr int BM=128, BK=64, STR=72, S=3;
    constexpr int ABYTES = BM*STR*2, BBYTES = BN*STR*2;
    constexpr int BNW = BN/2, NP = BNW/16, NT8 = BNW/8;
    constexpr int APT = (BM*(BK/8))/256, BPT = (BN*(BK/8))/256;

    extern __shared__ char smem_[];
    const uint32_t sA = smem_u32(smem_);
    const uint32_t sB = sA + S*ABYTES;

    const int tid = threadIdx.x, lane = tid & 31, wid = tid >> 5;
    const int wm = wid & 3, wn = wid >> 2;
    const int m0 = blockIdx.y * BM, n0 = blockIdx.x * BN;

    float acc[2][NT8][4];
#pragma unroll
    for (int i = 0; i < 2; i++)
#pragma unroll
        for (int j = 0; j < NT8; j++)
#pragma unroll
            for (int q = 0; q < 4; q++) acc[i][j][q] = 0.f;

    const int NT = K / BK;

    auto load_tile = [&](int c, int buf){
        const int kk = c * BK;
#pragma unroll
        for (int p = 0; p < APT; p++) {
            int i = p*256 + tid, r = i >> 3, c8 = i & 7;
            cpasync16(sA + buf*ABYTES + (r*STR + c8*8)*2,
                      Ah + (size_t)(m0 + r)*K + kk + c8*8);
        }
#pragma unroll
        for (int p = 0; p < BPT; p++) {
            int i = p*256 + tid, r = i >> 3, c8 = i & 7;
            cpasync16(sB + buf*BBYTES + (r*STR + c8*8)*2,
                      Bh + (size_t)(n0 + r)*K + kk + c8*8);
        }
        CP_COMMIT();
    };

    const int aRow = wm*32 + (lane & 15);
    const int aCol = (lane >> 4) * 8;
    const int bRow = wn*BNW + (lane & 7) + ((lane >> 4) & 1) * 8;
    const int bCol = ((lane >> 3) & 1) * 8;

    load_tile(0, 0);
    load_tile(1, 1);
    for (int c = 0; c < NT; ++c) {
        const int buf = c % S;
        CP_WAIT1();
        __syncthreads();
        if (c + 2 < NT) load_tile(c + 2, (c + 2) % S); else CP_COMMIT();

#pragma unroll
        for (int kk2 = 0; kk2 < BK; kk2 += 16) {
            uint32_t a[2][4];
#pragma unroll
            for (int mi = 0; mi < 2; mi++)
                ldsm4(a[mi], sA + buf*ABYTES + ((aRow + mi*16)*STR + kk2 + aCol)*2);
            uint32_t b[NP][4];
#pragma unroll
            for (int np = 0; np < NP; np++)
                ldsm4(b[np], sB + buf*BBYTES + ((bRow + np*16)*STR + kk2 + bCol)*2);
#pragma unroll
            for (int mi = 0; mi < 2; mi++)
#pragma unroll
                for (int np = 0; np < NP; np++) {
                    mma16816(acc[mi][2*np],   a[mi], b[np][0], b[np][1]);
                    mma16816(acc[mi][2*np+1], a[mi], b[np][2], b[np][3]);
                }
        }
    }

    const int g = lane >> 2, t = lane & 3;
    auto emit = [&](int row, int col, float v0, float v1){
        if constexpr (EPI == 4) {
            v0 += bias[col]; v1 += bias[col+1];
            v0 = v0 / (1.f + expf(-v0)); v1 = v1 / (1.f + expf(-v1));
            *reinterpret_cast<__half2*>(Ch + (size_t)row*Ngl + col) =
                __halves2half2(__float2half(v0), __float2half(v1));
        } else if constexpr (EPI == 0) {
            float2 o; o.x = v0 + bias[col]; o.y = v1 + bias[col+1];
            *reinterpret_cast<float2*>(Cf + (size_t)row*Ngl + col) = o;
        } else if constexpr (EPI == 5) {
            size_t orow = (size_t)((row % Tsw) * Bsw + row / Tsw);
            float o0 = v0 + bias[col] + bias2[col];
            float o1 = v1 + bias[col+1] + bias2[col+1];
            *reinterpret_cast<__half2*>(Ch + orow*(size_t)Ngl + col) =
                __halves2half2(__float2half(o0), __float2half(o1));
        } else { // EPI == 6
            if (col < cA) {
                float2 o; o.x = v0 + bias[col]; o.y = v1 + bias[col+1];
                *reinterpret_cast<float2*>(Cf + (size_t)row*cA + col) = o;
            } else {
                int c2 = col - cA;
                float2 o; o.x = v0 + bias2[c2]; o.y = v1 + bias2[c2+1];
                *reinterpret_cast<float2*>(Cf2 + (size_t)row*cOBS + c2) = o;
            }
        }
    };
#pragma unroll
    for (int mi = 0; mi < 2; mi++)
#pragma unroll
        for (int ni = 0; ni < NT8; ni++) {
            int row = m0 + wm*32 + mi*16 + g;
            int col = n0 + wn*BNW + ni*8 + 2*t;
            emit(row,     col, acc[mi][ni][0], acc[mi][ni][1]);
            emit(row + 8, col, acc[mi][ni][2], acc[mi][ni][3]);
        }
}

// ---------------------------------------------------------------------------
// Fused LSTM step (R14 winner): single-segment fp16 gates GEMM
// (128x64 tile: 4 gates x 16 j) + cell update. grid (cH/16, cB/128).
// Final step writes hT/cT directly to output.
// ---------------------------------------------------------------------------
__global__ void __launch_bounds__(256)
scan_step_k(const f16* __restrict__ hih, const f16* __restrict__ Bw,
            const f16* __restrict__ gxt, const float* __restrict__ cin,
            float* __restrict__ cout, f16* __restrict__ hoh,
            float* __restrict__ hseq, int t,
            float* __restrict__ outh, float* __restrict__ outc)
{
    constexpr int BM=128, BN=64, BK=64, STR=72, S=3, K=cH;
    constexpr int ABYTES = BM*STR*2, BBYTES = BN*STR*2;
    constexpr int BNW=32, NP=2, NT8=4;

    extern __shared__ char smem_[];
    const uint32_t sA = smem_u32(smem_);
    const uint32_t sB = sA + S*ABYTES;
    float* sg = reinterpret_cast<float*>(smem_);   // epilogue alias: [128][66]

    const int tid = threadIdx.x, lane = tid & 31, wid = tid >> 5;
    const int wm = wid & 3, wn = wid >> 2;
    const int m0 = blockIdx.y * BM, j0 = blockIdx.x * 16;

    float acc[2][NT8][4];
#pragma unroll
    for (int i = 0; i < 2; i++)
#pragma unroll
        for (int j = 0; j < NT8; j++)
#pragma unroll
            for (int q = 0; q < 4; q++) acc[i][j][q] = 0.f;

    const int NT = K / BK;   // 16

    auto load_tile = [&](int c, int buf){
        const int kk = c * BK;
#pragma unroll
        for (int p = 0; p < 4; p++) {
            int i = p*256 + tid, r = i >> 3, c8 = i & 7;
            cpasync16(sA + buf*ABYTES + (r*STR + c8*8)*2,
                      hih + (size_t)(m0 + r)*K + kk + c8*8);
        }
#pragma unroll
        for (int p = 0; p < 2; p++) {
            int i = p*256 + tid, r = i >> 3, c8 = i & 7;
            int grow = (r >> 4)*cH + j0 + (r & 15);
            cpasync16(sB + buf*BBYTES + (r*STR + c8*8)*2,
                      Bw + (size_t)grow*K + kk + c8*8);
        }
        CP_COMMIT();
    };

    const int aRow = wm*32 + (lane & 15);
    const int aCol = (lane >> 4) * 8;
    const int bRow = wn*BNW + (lane & 7) + ((lane >> 4) & 1) * 8;
    const int bCol = ((lane >> 3) & 1) * 8;

    load_tile(0, 0);
    load_tile(1, 1);
    for (int c = 0; c < NT; ++c) {
        const int buf = c % S;
        CP_WAIT1();
        __syncthreads();
        if (c + 2 < NT) load_tile(c + 2, (c + 2) % S); else CP_COMMIT();
#pragma unroll
        for (int kk2 = 0; kk2 < BK; kk2 += 16) {
            uint32_t a[2][4];
#pragma unroll
            for (int mi = 0; mi < 2; mi++)
                ldsm4(a[mi], sA + buf*ABYTES + ((aRow + mi*16)*STR + kk2 + aCol)*2);
            uint32_t b[NP][4];
#pragma unroll
            for (int np = 0; np < NP; np++)
                ldsm4(b[np], sB + buf*BBYTES + ((bRow + np*16)*STR + kk2 + bCol)*2);
#pragma unroll
            for (int mi = 0; mi < 2; mi++)
#pragma unroll
                for (int np = 0; np < NP; np++) {
                    mma16816(acc[mi][2*np],   a[mi], b[np][0], b[np][1]);
                    mma16816(acc[mi][2*np+1], a[mi], b[np][2], b[np][3]);
                }
        }
    }
    __syncthreads();   // all ldsm done before smem alias reuse

    const int g_ = lane >> 2, t_ = lane & 3;
#pragma unroll
    for (int mi = 0; mi < 2; mi++)
#pragma unroll
        for (int ni = 0; ni < NT8; ni++) {
            int rowl = wm*32 + mi*16 + g_;
            int col  = wn*BNW + ni*8 + 2*t_;
            int gate = col >> 4, jj = col & 15;
#pragma unroll
            for (int half = 0; half < 2; half++) {
                int rr = rowl + half*8;
                __half2 gxh = *reinterpret_cast<const __half2*>(
                    gxt + (size_t)(m0+rr)*cG + gate*cH + j0 + jj);
                float2 gxv = __half22float2(gxh);
                sg[rr*66 + col]     = acc[mi][ni][2*half]   + gxv.x;
                sg[rr*66 + col + 1] = acc[mi][ni][2*half+1] + gxv.y;
            }
        }
    __syncthreads();

    const bool last = (t == cT - 1);
#pragma unroll
    for (int k = 0; k < 8; k++) {
        int idx = tid + k*256;
        int row = idx & 127, jj = idx >> 7;
        float i_ = sigm_(sg[row*66 + jj]);
        float f_ = sigm_(sg[row*66 + 16 + jj]);
        float g2 = tanhf(sg[row*66 + 32 + jj]);
        float o_ = sigm_(sg[row*66 + 48 + jj]);
        size_t ci = (size_t)(m0+row)*cH + j0 + jj;
        float cc = f_ * cin[ci] + i_ * g2;
        float hv = o_ * tanhf(cc);
        hseq[((size_t)(m0+row)*cT + t)*cH + j0 + jj] = hv;
        if (last) {
            outh[ci] = hv;
            outc[ci] = cc;
        } else {
            cout[ci] = cc;
            hoh[ci] = __float2half(hv);
        }
    }
}

// ---------------- conversion / pointwise kernels ----------------
__global__ void conv_h_k(const float* __restrict__ in, f16* __restrict__ o, size_t n4)
{
    size_t i = (size_t)blockIdx.x*blockDim.x + threadIdx.x;
    if (i >= n4) return;
    float4 v = reinterpret_cast<const float4*>(in)[i];
    reinterpret_cast<__half2*>(o)[i*2]   = __halves2half2(__float2half(v.x), __float2half(v.y));
    reinterpret_cast<__half2*>(o)[i*2+1] = __halves2half2(__float2half(v.z), __float2half(v.w));
}
__global__ void convT_k(const float* __restrict__ W, f16* __restrict__ o, int K, int N)
{
    __shared__ float t[32][33];
    int tx = threadIdx.x, ty = threadIdx.y;
#pragma unroll
    for (int r = 0; r < 4; r++)
        t[ty+8*r][tx] = W[(size_t)(blockIdx.y*32 + ty + 8*r)*N + blockIdx.x*32 + tx];
    __syncthreads();
#pragma unroll
    for (int r = 0; r < 4; r++) {
        int n = blockIdx.x*32 + ty + 8*r, k = blockIdx.y*32 + tx;
        o[(size_t)n*K + k] = __float2half(t[tx][ty+8*r]);
    }
}
// Fused layernorm + xh(f16) output + values/rew GEMV (fp32-exact from y regs)
__global__ void ln_head_k(const float* __restrict__ in, f16* __restrict__ oh,
                          const float* __restrict__ gw, const float* __restrict__ bw,
                          const float* __restrict__ wc, const float* __restrict__ wr,
                          const float* __restrict__ bc, const float* __restrict__ br,
                          float* __restrict__ outv, float* __restrict__ outr)
{
    const int row = blockIdx.x;
    const float* x = in + (size_t)row*cH;
    const int i = threadIdx.x*4;
    float4 v = *reinterpret_cast<const float4*>(x + i);
    float s  = v.x + v.y + v.z + v.w;
    float ss = v.x*v.x + v.y*v.y + v.z*v.z + v.w*v.w;

    __shared__ float red[64];
    int w = threadIdx.x/32, lane = threadIdx.x%32;
    for (int o = 16; o > 0; o >>= 1) { s += __shfl_xor_sync(~0u,s,o); ss += __shfl_xor_sync(~0u,ss,o); }
    if (lane == 0) { red[w] = s; red[32+w] = ss; }
    __syncthreads();
    if (threadIdx.x < 32) {
        float a = (threadIdx.x < 8) ? red[threadIdx.x] : 0.f;
        float b = (threadIdx.x < 8) ? red[32+threadIdx.x] : 0.f;
        for (int o = 4; o > 0; o >>= 1) { a += __shfl_xor_sync(~0u,a,o); b += __shfl_xor_sync(~0u,b,o); }
        if (threadIdx.x == 0) { red[0] = a; red[1] = b; }
    }
    __syncthreads();
    float mu = red[0]/cH, var = red[1]/cH - mu*mu, rstd = rsqrtf(var + 1e-5f);

    float4 gv = *reinterpret_cast<const float4*>(gw + i);
    float4 bv = *reinterpret_cast<const float4*>(bw + i);
    float y0 = (v.x-mu)*rstd*gv.x + bv.x;
    float y1 = (v.y-mu)*rstd*gv.y + bv.y;
    float y2 = (v.z-mu)*rstd*gv.z + bv.z;
    float y3 = (v.w-mu)*rstd*gv.w + bv.w;

    __half2 h01 = __halves2half2(__float2half(y0), __float2half(y1));
    __half2 h23 = __halves2half2(__float2half(y2), __float2half(y3));
    *reinterpret_cast<uint2*>(oh + (size_t)row*cH + i) =
        make_uint2(*reinterpret_cast<uint32_t*>(&h01), *reinterpret_cast<uint32_t*>(&h23));

    float4 cv = *reinterpret_cast<const float4*>(wc + i);
    float4 rv = *reinterpret_cast<const float4*>(wr + i);
    float sc = y0*cv.x + y1*cv.y + y2*cv.z + y3*cv.w;
    float sr = y0*rv.x + y1*rv.y + y2*rv.z + y3*rv.w;
    __syncthreads();   // red reuse
    for (int o = 16; o > 0; o >>= 1) { sc += __shfl_xor_sync(~0u,sc,o); sr += __shfl_xor_sync(~0u,sr,o); }
    if (lane == 0) { red[w] = sc; red[32+w] = sr; }
    __syncthreads();
    if (threadIdx.x == 0) {
        float a = 0.f, b = 0.f;
#pragma unroll
        for (int q = 0; q < 8; q++) { a += red[q]; b += red[32+q]; }
        outv[row] = a + bc[0];
        outr[row] = b + br[0];
    }
}

// ---------------------------------------------------------------------------
extern "C" void kernel_launch(void* const* d_in, const int* in_sizes, int n_in,
                              void* d_out, int out_size)
{
    const float* obs  = (const float*)d_in[0];
    const float* h0   = (const float*)d_in[1];
    const float* c0   = (const float*)d_in[2];
    const float* W1   = (const float*)d_in[3];
    const float* b1   = (const float*)d_in[4];
    const float* W2   = (const float*)d_in[5];
    const float* b2   = (const float*)d_in[6];
    const float* w_ih = (const float*)d_in[7];
    const float* w_hh = (const float*)d_in[8];
    const float* b_ih = (const float*)d_in[9];
    const float* b_hh = (const float*)d_in[10];
    const float* ln_g = (const float*)d_in[11];
    const float* ln_b = (const float*)d_in[12];
    const float* Wa   = (const float*)d_in[13];
    const float* ba   = (const float*)d_in[14];
    const float* Wc   = (const float*)d_in[15];
    const float* bc   = (const float*)d_in[16];
    const float* Wobs = (const float*)d_in[17];
    const float* bobs = (const float*)d_in[18];
    const float* Wr   = (const float*)d_in[19];
    const float* br   = (const float*)d_in[20];
    float* out = (float*)d_out;

    f16 *obs_h,*e1h,*e2h,*xh,*hh0,*hh1,*gx;
    f16 *w1,*w2,*whd,*wih,*whh;
    float *hseq,*cbuf;
    cudaGetSymbolAddress((void**)&obs_h, g_obs_h);
    cudaGetSymbolAddress((void**)&e1h, g_e1h);
    cudaGetSymbolAddress((void**)&e2h, g_e2h);
    cudaGetSymbolAddress((void**)&xh, g_xh);
    cudaGetSymbolAddress((void**)&hh0, g_hh0); cudaGetSymbolAddress((void**)&hh1, g_hh1);
    cudaGetSymbolAddress((void**)&w1, g_w1);   cudaGetSymbolAddress((void**)&w2, g_w2);
    cudaGetSymbolAddress((void**)&whd, g_whd);
    cudaGetSymbolAddress((void**)&wih, g_wih); cudaGetSymbolAddress((void**)&whh, g_whh);
    cudaGetSymbolAddress((void**)&gx, g_gx);   cudaGetSymbolAddress((void**)&hseq, g_hseq);
    cudaGetSymbolAddress((void**)&cbuf, g_c);

    const int SM128 = 3*(128*72*2 + 128*72*2);   // 110592
    const int SM64  = 3*(128*72*2 + 64*72*2);    // 82944
    cudaFuncSetAttribute(tgemm_k<128,4>, cudaFuncAttributeMaxDynamicSharedMemorySize, SM128);
    cudaFuncSetAttribute(tgemm_k<128,5>, cudaFuncAttributeMaxDynamicSharedMemorySize, SM128);
    cudaFuncSetAttribute(tgemm_k<64,6>,  cudaFuncAttributeMaxDynamicSharedMemorySize, SM64);
    cudaFuncSetAttribute(scan_step_k,    cudaFuncAttributeMaxDynamicSharedMemorySize, SM64);

    // conversions (all single fp16)
    conv_h_k<<<((size_t)cBT*cOBS/4 + 255)/256, 256>>>(obs, obs_h, (size_t)cBT*cOBS/4);
    conv_h_k<<<((size_t)cB*cH/4 + 255)/256, 256>>>(h0, hh0, (size_t)cB*cH/4);
    conv_h_k<<<((size_t)cG*cE/4 + 255)/256, 256>>>(w_ih, wih, (size_t)cG*cE/4);
    conv_h_k<<<((size_t)cG*cH/4 + 255)/256, 256>>>(w_hh, whh, (size_t)cG*cH/4);
    { dim3 b(32,8);
      convT_k<<<dim3(cE/32, cOBS/32), b>>>(W1, w1, cOBS, cE);
      convT_k<<<dim3(cE/32, cE/32), b>>>(W2, w2, cE, cE);
      convT_k<<<dim3(cA/32, cH/32), b>>>(Wa, whd, cH, cA);
      convT_k<<<dim3(cOBS/32, cH/32), b>>>(Wobs, whd + (size_t)cA*cH, cH, cOBS); }

    // 1) enc1 = silu(obs @ W1 + b1)
    tgemm_k<128,4><<<dim3(cE/128, cBT/128), 256, SM128>>>(
        obs_h, w1, nullptr, nullptr, e1h, b1, nullptr, cE, cOBS, 0, 0);
    // 2) enc2 = silu(enc1 @ W2 + b2)
    tgemm_k<128,4><<<dim3(cE/128, cBT/128), 256, SM128>>>(
        e1h, w2, nullptr, nullptr, e2h, b2, nullptr, cE, cE, 0, 0);
    // 3) gx = enc2 @ w_ih^T + (b_ih + b_hh), stored [T,B,4H] f16
    tgemm_k<128,5><<<dim3(cG/128, cBT/128), 256, SM128>>>(
        e2h, wih, nullptr, nullptr, gx, b_ih, b_hh, cG, cE, cT, cB);
    // 4) fused scan (per-step launches; last step writes hT/cT to out)
    for (int t = 0; t < cT; ++t) {
        const f16* hi = (t & 1) ? hh1 : hh0;
        f16* ho = (t & 1) ? hh0 : hh1;
        scan_step_k<<<dim3(cH/16, cB/128), 256, SM64>>>(
            hi, whh, gx + (size_t)t*cB*cG, (t == 0) ? c0 : cbuf, cbuf, ho, hseq, t,
            out + OFF_HT, out + OFF_CT);
    }
    // 5) fused layernorm + xh + values/rew
    ln_head_k<<<cBT, 256>>>(hseq, xh, ln_g, ln_b, Wc, Wr, bc, br,
                            out + OFF_VAL, out + OFF_REW);
    // 6+7) combined heads: [logits | obs_pred] = xh @ [Wa;Wobs]^T, N=576
    tgemm_k<64,6><<<dim3((cA+cOBS)/64, cBT/128), 256, SM64>>>(
        xh, whd, out + OFF_LOGITS, out + OFF_OBS, nullptr, ba, bobs, cA+cOBS, cH, 0, 0);
}

// round 17
// speedup vs baseline: 1.3620x; 1.0036x over previous
#include <cuda_runtime.h>
#include <cuda_fp16.h>
#include <cstdint>
#include <cstddef>

constexpr int cB=256, cT=128, cOBS=512, cE=1024, cH=1024, cA=64;
constexpr int cBT=cB*cT, cG=4*cH;

constexpr size_t OFF_LOGITS=0;
constexpr size_t OFF_VAL = OFF_LOGITS + (size_t)cBT*cA;
constexpr size_t OFF_OBS = OFF_VAL + (size_t)cBT;
constexpr size_t OFF_REW = OFF_OBS + (size_t)cBT*cOBS;
constexpr size_t OFF_HT  = OFF_REW + (size_t)cBT;
constexpr size_t OFF_CT  = OFF_HT + (size_t)cB*cH;

typedef __half f16;
// activations
__device__ f16 g_obs_h[(size_t)cBT*cOBS];
__device__ f16 g_e1h[(size_t)cBT*cE];
__device__ f16 g_e2h[(size_t)cBT*cE];
__device__ f16 g_xh[(size_t)cBT*cH];
__device__ f16 g_hh0[(size_t)cB*cH], g_hh1[(size_t)cB*cH];
__device__ f16 g_gx[(size_t)cBT*cG];       // [T,B,4H] f16
__device__ float g_hseq[(size_t)cBT*cH];   // [B,T,H] fp32
__device__ float g_c[(size_t)cB*cH];
// weights ([N,K])
__device__ f16 g_w1[(size_t)cE*cOBS];
__device__ f16 g_w2[(size_t)cE*cE];
__device__ f16 g_whd[(size_t)(cA+cOBS)*cH];   // combined [Wa ; Wobs]
__device__ f16 g_wih[(size_t)cG*cE];
__device__ f16 g_whh[(size_t)cG*cH];

__device__ __forceinline__ uint32_t smem_u32(const void* p){
    uint32_t a; asm("{ .reg .u64 t; cvta.to.shared.u64 t, %1; cvt.u32.u64 %0, t; }":"=r"(a):"l"(p)); return a;
}
__device__ __forceinline__ void cpasync16(uint32_t d, const void* g){
    asm volatile("cp.async.cg.shared.global [%0], [%1], 16;"::"r"(d),"l"(g):"memory");
}
#define CP_COMMIT() asm volatile("cp.async.commit_group;" ::: "memory")
#define CP_WAIT1()  asm volatile("cp.async.wait_group 1;" ::: "memory")
__device__ __forceinline__ void ldsm4(uint32_t (&r)[4], uint32_t a){
    asm volatile("ldmatrix.sync.aligned.m8n8.x4.shared.b16 {%0,%1,%2,%3}, [%4];"
        : "=r"(r[0]),"=r"(r[1]),"=r"(r[2]),"=r"(r[3]) : "r"(a));
}
__device__ __forceinline__ void mma16816(float (&d)[4], const uint32_t (&a)[4],
                                         uint32_t b0, uint32_t b1){
    asm volatile("mma.sync.aligned.m16n8k16.row.col.f32.f16.f16.f32 "
        "{%0,%1,%2,%3}, {%4,%5,%6,%7}, {%8,%9}, {%0,%1,%2,%3};"
        : "+f"(d[0]),"+f"(d[1]),"+f"(d[2]),"+f"(d[3])
        : "r"(a[0]),"r"(a[1]),"r"(a[2]),"r"(a[3]),"r"(b0),"r"(b1));
}
__device__ __forceinline__ float sigm_(float x){ return 1.f/(1.f+expf(-x)); }

// ---------------------------------------------------------------------------
// fp16 tensor GEMM, BK=64, 3-stage cp.async pipeline, single segment Ah*Bh.
// EPI: 0=+bias->f32 ; 4=silu(+bias)->single f16 ;
//      5=+bias+bias2, row swizzle r->(r%Tsw)*Bsw+r/Tsw -> f16 (gx) ;
//      6=split heads: col<64 -> Cf[row*64+col]+bias ; else Cf2[row*512+col-64]+bias2
// ---------------------------------------------------------------------------
template<int BN, int EPI>
__global__ void __launch_bounds__(256, 2)
tgemm_k(const f16* __restrict__ Ah, const f16* __restrict__ Bh,
        float* __restrict__ Cf, float* __restrict__ Cf2, f16* __restrict__ Ch,
        const float* __restrict__ bias, const float* __restrict__ bias2,
        int Ngl, int K, int Tsw, int Bsw)
{
    constexpr int BM=128, BK=64, STR=72, S=3;
    constexpr int ABYTES = BM*STR*2, BBYTES = BN*STR*2;
    constexpr int BNW = BN/2, NP = BNW/16, NT8 = BNW/8;
    constexpr int APT = (BM*(BK/8))/256, BPT = (BN*(BK/8))/256;

    extern __shared__ char smem_[];
    const uint32_t sA = smem_u32(smem_);
    const uint32_t sB = sA + S*ABYTES;

    const int tid = threadIdx.x, lane = tid & 31, wid = tid >> 5;
    const int wm = wid & 3, wn = wid >> 2;
    const int m0 = blockIdx.y * BM, n0 = blockIdx.x * BN;

    float acc[2][NT8][4];
#pragma unroll
    for (int i = 0; i < 2; i++)
#pragma unroll
        for (int j = 0; j < NT8; j++)
#pragma unroll
            for (int q = 0; q < 4; q++) acc[i][j][q] = 0.f;

    const int NT = K / BK;

    auto load_tile = [&](int c, int buf){
        const int kk = c * BK;
#pragma unroll
        for (int p = 0; p < APT; p++) {
            int i = p*256 + tid, r = i >> 3, c8 = i & 7;
            cpasync16(sA + buf*ABYTES + (r*STR + c8*8)*2,
                      Ah + (size_t)(m0 + r)*K + kk + c8*8);
        }
#pragma unroll
        for (int p = 0; p < BPT; p++) {
            int i = p*256 + tid, r = i >> 3, c8 = i & 7;
            cpasync16(sB + buf*BBYTES + (r*STR + c8*8)*2,
                      Bh + (size_t)(n0 + r)*K + kk + c8*8);
        }
        CP_COMMIT();
    };

    const int aRow = wm*32 + (lane & 15);
    const int aCol = (lane >> 4) * 8;
    const int bRow = wn*BNW + (lane & 7) + ((lane >> 4) & 1) * 8;
    const int bCol = ((lane >> 3) & 1) * 8;

    load_tile(0, 0);
    load_tile(1, 1);
    for (int c = 0; c < NT; ++c) {
        const int buf = c % S;
        CP_WAIT1();
        __syncthreads();
        if (c + 2 < NT) load_tile(c + 2, (c + 2) % S); else CP_COMMIT();

#pragma unroll
        for (int kk2 = 0; kk2 < BK; kk2 += 16) {
            uint32_t a[2][4];
#pragma unroll
            for (int mi = 0; mi < 2; mi++)
                ldsm4(a[mi], sA + buf*ABYTES + ((aRow + mi*16)*STR + kk2 + aCol)*2);
            uint32_t b[NP][4];
#pragma unroll
            for (int np = 0; np < NP; np++)
                ldsm4(b[np], sB + buf*BBYTES + ((bRow + np*16)*STR + kk2 + bCol)*2);
#pragma unroll
            for (int mi = 0; mi < 2; mi++)
#pragma unroll
                for (int np = 0; np < NP; np++) {
                    mma16816(acc[mi][2*np],   a[mi], b[np][0], b[np][1]);
                    mma16816(acc[mi][2*np+1], a[mi], b[np][2], b[np][3]);
                }
        }
    }

    const int g = lane >> 2, t = lane & 3;
    auto emit = [&](int row, int col, float v0, float v1){
        if constexpr (EPI == 4) {
            v0 += bias[col]; v1 += bias[col+1];
            v0 = v0 / (1.f + expf(-v0)); v1 = v1 / (1.f + expf(-v1));
            *reinterpret_cast<__half2*>(Ch + (size_t)row*Ngl + col) =
                __halves2half2(__float2half(v0), __float2half(v1));
        } else if constexpr (EPI == 0) {
            float2 o; o.x = v0 + bias[col]; o.y = v1 + bias[col+1];
            *reinterpret_cast<float2*>(Cf + (size_t)row*Ngl + col) = o;
        } else if constexpr (EPI == 5) {
            size_t orow = (size_t)((row % Tsw) * Bsw + row / Tsw);
            float o0 = v0 + bias[col] + bias2[col];
            float o1 = v1 + bias[col+1] + bias2[col+1];
            *reinterpret_cast<__half2*>(Ch + orow*(size_t)Ngl + col) =
                __halves2half2(__float2half(o0), __float2half(o1));
        } else { // EPI == 6
            if (col < cA) {
                float2 o; o.x = v0 + bias[col]; o.y = v1 + bias[col+1];
                *reinterpret_cast<float2*>(Cf + (size_t)row*cA + col) = o;
            } else {
                int c2 = col - cA;
                float2 o; o.x = v0 + bias2[c2]; o.y = v1 + bias2[c2+1];
                *reinterpret_cast<float2*>(Cf2 + (size_t)row*cOBS + c2) = o;
            }
        }
    };
#pragma unroll
    for (int mi = 0; mi < 2; mi++)
#pragma unroll
        for (int ni = 0; ni < NT8; ni++) {
            int row = m0 + wm*32 + mi*16 + g;
            int col = n0 + wn*BNW + ni*8 + 2*t;
            emit(row,     col, acc[mi][ni][0], acc[mi][ni][1]);
            emit(row + 8, col, acc[mi][ni][2], acc[mi][ni][3]);
        }
}

// ---------------------------------------------------------------------------
// Fused LSTM step (R14/R16 winner, unchanged): single-segment fp16 gates GEMM
// (128x64 tile: 4 gates x 16 j) + cell update. grid (cH/16, cB/128).
// Final step writes hT/cT directly to output.
// ---------------------------------------------------------------------------
__global__ void __launch_bounds__(256)
scan_step_k(const f16* __restrict__ hih, const f16* __restrict__ Bw,
            const f16* __restrict__ gxt, const float* __restrict__ cin,
            float* __restrict__ cout, f16* __restrict__ hoh,
            float* __restrict__ hseq, int t,
            float* __restrict__ outh, float* __restrict__ outc)
{
    constexpr int BM=128, BN=64, BK=64, STR=72, S=3, K=cH;
    constexpr int ABYTES = BM*STR*2, BBYTES = BN*STR*2;
    constexpr int BNW=32, NP=2, NT8=4;

    extern __shared__ char smem_[];
    const uint32_t sA = smem_u32(smem_);
    const uint32_t sB = sA + S*ABYTES;
    float* sg = reinterpret_cast<float*>(smem_);   // epilogue alias: [128][66]

    const int tid = threadIdx.x, lane = tid & 31, wid = tid >> 5;
    const int wm = wid & 3, wn = wid >> 2;
    const int m0 = blockIdx.y * BM, j0 = blockIdx.x * 16;

    float acc[2][NT8][4];
#pragma unroll
    for (int i = 0; i < 2; i++)
#pragma unroll
        for (int j = 0; j < NT8; j++)
#pragma unroll
            for (int q = 0; q < 4; q++) acc[i][j][q] = 0.f;

    const int NT = K / BK;   // 16

    auto load_tile = [&](int c, int buf){
        const int kk = c * BK;
#pragma unroll
        for (int p = 0; p < 4; p++) {
            int i = p*256 + tid, r = i >> 3, c8 = i & 7;
            cpasync16(sA + buf*ABYTES + (r*STR + c8*8)*2,
                      hih + (size_t)(m0 + r)*K + kk + c8*8);
        }
#pragma unroll
        for (int p = 0; p < 2; p++) {
            int i = p*256 + tid, r = i >> 3, c8 = i & 7;
            int grow = (r >> 4)*cH + j0 + (r & 15);
            cpasync16(sB + buf*BBYTES + (r*STR + c8*8)*2,
                      Bw + (size_t)grow*K + kk + c8*8);
        }
        CP_COMMIT();
    };

    const int aRow = wm*32 + (lane & 15);
    const int aCol = (lane >> 4) * 8;
    const int bRow = wn*BNW + (lane & 7) + ((lane >> 4) & 1) * 8;
    const int bCol = ((lane >> 3) & 1) * 8;

    load_tile(0, 0);
    load_tile(1, 1);
    for (int c = 0; c < NT; ++c) {
        const int buf = c % S;
        CP_WAIT1();
        __syncthreads();
        if (c + 2 < NT) load_tile(c + 2, (c + 2) % S); else CP_COMMIT();
#pragma unroll
        for (int kk2 = 0; kk2 < BK; kk2 += 16) {
            uint32_t a[2][4];
#pragma unroll
            for (int mi = 0; mi < 2; mi++)
                ldsm4(a[mi], sA + buf*ABYTES + ((aRow + mi*16)*STR + kk2 + aCol)*2);
            uint32_t b[NP][4];
#pragma unroll
            for (int np = 0; np < NP; np++)
                ldsm4(b[np], sB + buf*BBYTES + ((bRow + np*16)*STR + kk2 + bCol)*2);
#pragma unroll
            for (int mi = 0; mi < 2; mi++)
#pragma unroll
                for (int np = 0; np < NP; np++) {
                    mma16816(acc[mi][2*np],   a[mi], b[np][0], b[np][1]);
                    mma16816(acc[mi][2*np+1], a[mi], b[np][2], b[np][3]);
                }
        }
    }
    __syncthreads();   // all ldsm done before smem alias reuse

    const int g_ = lane >> 2, t_ = lane & 3;
#pragma unroll
    for (int mi = 0; mi < 2; mi++)
#pragma unroll
        for (int ni = 0; ni < NT8; ni++) {
            int rowl = wm*32 + mi*16 + g_;
            int col  = wn*BNW + ni*8 + 2*t_;
            int gate = col >> 4, jj = col & 15;
#pragma unroll
            for (int half = 0; half < 2; half++) {
                int rr = rowl + half*8;
                __half2 gxh = *reinterpret_cast<const __half2*>(
                    gxt + (size_t)(m0+rr)*cG + gate*cH + j0 + jj);
                float2 gxv = __half22float2(gxh);
                sg[rr*66 + col]     = acc[mi][ni][2*half]   + gxv.x;
                sg[rr*66 + col + 1] = acc[mi][ni][2*half+1] + gxv.y;
            }
        }
    __syncthreads();

    const bool last = (t == cT - 1);
#pragma unroll
    for (int k = 0; k < 8; k++) {
        int idx = tid + k*256;
        int row = idx & 127, jj = idx >> 7;
        float i_ = sigm_(sg[row*66 + jj]);
        float f_ = sigm_(sg[row*66 + 16 + jj]);
        float g2 = tanhf(sg[row*66 + 32 + jj]);
        float o_ = sigm_(sg[row*66 + 48 + jj]);
        size_t ci = (size_t)(m0+row)*cH + j0 + jj;
        float cc = f_ * cin[ci] + i_ * g2;
        float hv = o_ * tanhf(cc);
        hseq[((size_t)(m0+row)*cT + t)*cH + j0 + jj] = hv;
        if (last) {
            outh[ci] = hv;
            outc[ci] = cc;
        } else {
            cout[ci] = cc;
            hoh[ci] = __float2half(hv);
        }
    }
}

// ---------------- conversion / pointwise kernels ----------------
// Single merged fp32->f16 conversion over 4 segments (obs, h0, w_ih, w_hh).
__global__ void conv_all_k(const float* __restrict__ in0, f16* __restrict__ o0, size_t n0,
                           const float* __restrict__ in1, f16* __restrict__ o1, size_t n1,
                           const float* __restrict__ in2, f16* __restrict__ o2, size_t n2,
                           const float* __restrict__ in3, f16* __restrict__ o3, size_t n3)
{
    size_t i = (size_t)blockIdx.x*blockDim.x + threadIdx.x;   // float4 index
    const float* in; f16* o; size_t loc = i;
    if (loc < n0)      { in = in0; o = o0; }
    else { loc -= n0;
    if (loc < n1)      { in = in1; o = o1; }
    else { loc -= n1;
    if (loc < n2)      { in = in2; o = o2; }
    else { loc -= n2;
    if (loc < n3)      { in = in3; o = o3; }
    else return; } } }
    float4 v = reinterpret_cast<const float4*>(in)[loc];
    reinterpret_cast<__half2*>(o)[loc*2]   = __halves2half2(__float2half(v.x), __float2half(v.y));
    reinterpret_cast<__half2*>(o)[loc*2+1] = __halves2half2(__float2half(v.z), __float2half(v.w));
}
__global__ void convT_k(const float* __restrict__ W, f16* __restrict__ o, int K, int N)
{
    __shared__ float t[32][33];
    int tx = threadIdx.x, ty = threadIdx.y;
#pragma unroll
    for (int r = 0; r < 4; r++)
        t[ty+8*r][tx] = W[(size_t)(blockIdx.y*32 + ty + 8*r)*N + blockIdx.x*32 + tx];
    __syncthreads();
#pragma unroll
    for (int r = 0; r < 4; r++) {
        int n = blockIdx.x*32 + ty + 8*r, k = blockIdx.y*32 + tx;
        o[(size_t)n*K + k] = __float2half(t[tx][ty+8*r]);
    }
}
// Fused layernorm + xh(f16) output + values/rew GEMV (fp32-exact from y regs)
__global__ void ln_head_k(const float* __restrict__ in, f16* __restrict__ oh,
                          const float* __restrict__ gw, const float* __restrict__ bw,
                          const float* __restrict__ wc, const float* __restrict__ wr,
                          const float* __restrict__ bc, const float* __restrict__ br,
                          float* __restrict__ outv, float* __restrict__ outr)
{
    const int row = blockIdx.x;
    const float* x = in + (size_t)row*cH;
    const int i = threadIdx.x*4;
    float4 v = *reinterpret_cast<const float4*>(x + i);
    float s  = v.x + v.y + v.z + v.w;
    float ss = v.x*v.x + v.y*v.y + v.z*v.z + v.w*v.w;

    __shared__ float red[64];
    int w = threadIdx.x/32, lane = threadIdx.x%32;
    for (int o = 16; o > 0; o >>= 1) { s += __shfl_xor_sync(~0u,s,o); ss += __shfl_xor_sync(~0u,ss,o); }
    if (lane == 0) { red[w] = s; red[32+w] = ss; }
    __syncthreads();
    if (threadIdx.x < 32) {
        float a = (threadIdx.x < 8) ? red[threadIdx.x] : 0.f;
        float b = (threadIdx.x < 8) ? red[32+threadIdx.x] : 0.f;
        for (int o = 4; o > 0; o >>= 1) { a += __shfl_xor_sync(~0u,a,o); b += __shfl_xor_sync(~0u,b,o); }
        if (threadIdx.x == 0) { red[0] = a; red[1] = b; }
    }
    __syncthreads();
    float mu = red[0]/cH, var = red[1]/cH - mu*mu, rstd = rsqrtf(var + 1e-5f);

    float4 gv = *reinterpret_cast<const float4*>(gw + i);
    float4 bv = *reinterpret_cast<const float4*>(bw + i);
    float y0 = (v.x-mu)*rstd*gv.x + bv.x;
    float y1 = (v.y-mu)*rstd*gv.y + bv.y;
    float y2 = (v.z-mu)*rstd*gv.z + bv.z;
    float y3 = (v.w-mu)*rstd*gv.w + bv.w;

    __half2 h01 = __halves2half2(__float2half(y0), __float2half(y1));
    __half2 h23 = __halves2half2(__float2half(y2), __float2half(y3));
    *reinterpret_cast<uint2*>(oh + (size_t)row*cH + i) =
        make_uint2(*reinterpret_cast<uint32_t*>(&h01), *reinterpret_cast<uint32_t*>(&h23));

    float4 cv = *reinterpret_cast<const float4*>(wc + i);
    float4 rv = *reinterpret_cast<const float4*>(wr + i);
    float sc = y0*cv.x + y1*cv.y + y2*cv.z + y3*cv.w;
    float sr = y0*rv.x + y1*rv.y + y2*rv.z + y3*rv.w;
    __syncthreads();   // red reuse
    for (int o = 16; o > 0; o >>= 1) { sc += __shfl_xor_sync(~0u,sc,o); sr += __shfl_xor_sync(~0u,sr,o); }
    if (lane == 0) { red[w] = sc; red[32+w] = sr; }
    __syncthreads();
    if (threadIdx.x == 0) {
        float a = 0.f, b = 0.f;
#pragma unroll
        for (int q = 0; q < 8; q++) { a += red[q]; b += red[32+q]; }
        outv[row] = a + bc[0];
        outr[row] = b + br[0];
    }
}

// ---------------------------------------------------------------------------
extern "C" void kernel_launch(void* const* d_in, const int* in_sizes, int n_in,
                              void* d_out, int out_size)
{
    const float* obs  = (const float*)d_in[0];
    const float* h0   = (const float*)d_in[1];
    const float* c0   = (const float*)d_in[2];
    const float* W1   = (const float*)d_in[3];
    const float* b1   = (const float*)d_in[4];
    const float* W2   = (const float*)d_in[5];
    const float* b2   = (const float*)d_in[6];
    const float* w_ih = (const float*)d_in[7];
    const float* w_hh = (const float*)d_in[8];
    const float* b_ih = (const float*)d_in[9];
    const float* b_hh = (const float*)d_in[10];
    const float* ln_g = (const float*)d_in[11];
    const float* ln_b = (const float*)d_in[12];
    const float* Wa   = (const float*)d_in[13];
    const float* ba   = (const float*)d_in[14];
    const float* Wc   = (const float*)d_in[15];
    const float* bc   = (const float*)d_in[16];
    const float* Wobs = (const float*)d_in[17];
    const float* bobs = (const float*)d_in[18];
    const float* Wr   = (const float*)d_in[19];
    const float* br   = (const float*)d_in[20];
    float* out = (float*)d_out;

    f16 *obs_h,*e1h,*e2h,*xh,*hh0,*hh1,*gx;
    f16 *w1,*w2,*whd,*wih,*whh;
    float *hseq,*cbuf;
    cudaGetSymbolAddress((void**)&obs_h, g_obs_h);
    cudaGetSymbolAddress((void**)&e1h, g_e1h);
    cudaGetSymbolAddress((void**)&e2h, g_e2h);
    cudaGetSymbolAddress((void**)&xh, g_xh);
    cudaGetSymbolAddress((void**)&hh0, g_hh0); cudaGetSymbolAddress((void**)&hh1, g_hh1);
    cudaGetSymbolAddress((void**)&w1, g_w1);   cudaGetSymbolAddress((void**)&w2, g_w2);
    cudaGetSymbolAddress((void**)&whd, g_whd);
    cudaGetSymbolAddress((void**)&wih, g_wih); cudaGetSymbolAddress((void**)&whh, g_whh);
    cudaGetSymbolAddress((void**)&gx, g_gx);   cudaGetSymbolAddress((void**)&hseq, g_hseq);
    cudaGetSymbolAddress((void**)&cbuf, g_c);

    const int SM128 = 3*(128*72*2 + 128*72*2);   // 110592
    const int SM64  = 3*(128*72*2 + 64*72*2);    // 82944
    cudaFuncSetAttribute(tgemm_k<128,4>, cudaFuncAttributeMaxDynamicSharedMemorySize, SM128);
    cudaFuncSetAttribute(tgemm_k<128,5>, cudaFuncAttributeMaxDynamicSharedMemorySize, SM128);
    cudaFuncSetAttribute(tgemm_k<64,6>,  cudaFuncAttributeMaxDynamicSharedMemorySize, SM64);
    cudaFuncSetAttribute(scan_step_k,    cudaFuncAttributeMaxDynamicSharedMemorySize, SM64);

    // merged conversions (obs, h0, w_ih, w_hh) in a single launch
    {
        const size_t n0 = (size_t)cBT*cOBS/4;   // obs float4 count
        const size_t n1 = (size_t)cB*cH/4;      // h0
        const size_t n2 = (size_t)cG*cE/4;      // w_ih
        const size_t n3 = (size_t)cG*cH/4;      // w_hh
        const size_t ntot = n0 + n1 + n2 + n3;
        conv_all_k<<<(unsigned)((ntot + 255)/256), 256>>>(
            obs, obs_h, n0, h0, hh0, n1, w_ih, wih, n2, w_hh, whh, n3);
    }
    { dim3 b(32,8);
      convT_k<<<dim3(cE/32, cOBS/32), b>>>(W1, w1, cOBS, cE);
      convT_k<<<dim3(cE/32, cE/32), b>>>(W2, w2, cE, cE);
      convT_k<<<dim3(cA/32, cH/32), b>>>(Wa, whd, cH, cA);
      convT_k<<<dim3(cOBS/32, cH/32), b>>>(Wobs, whd + (size_t)cA*cH, cH, cOBS); }

    // 1) enc1 = silu(obs @ W1 + b1)
    tgemm_k<128,4><<<dim3(cE/128, cBT/128), 256, SM128>>>(
        obs_h, w1, nullptr, nullptr, e1h, b1, nullptr, cE, cOBS, 0, 0);
    // 2) enc2 = silu(enc1 @ W2 + b2)
    tgemm_k<128,4><<<dim3(cE/128, cBT/128), 256, SM128>>>(
        e1h, w2, nullptr, nullptr, e2h, b2, nullptr, cE, cE, 0, 0);
    // 3) gx = enc2 @ w_ih^T + (b_ih + b_hh), stored [T,B,4H] f16
    tgemm_k<128,5><<<dim3(cG/128, cBT/128), 256, SM128>>>(
        e2h, wih, nullptr, nullptr, gx, b_ih, b_hh, cG, cE, cT, cB);
    // 4) fused scan (per-step launches; last step writes hT/cT to out)
    for (int t = 0; t < cT; ++t) {
        const f16* hi = (t & 1) ? hh1 : hh0;
        f16* ho = (t & 1) ? hh0 : hh1;
        scan_step_k<<<dim3(cH/16, cB/128), 256, SM64>>>(
            hi, whh, gx + (size_t)t*cB*cG, (t == 0) ? c0 : cbuf, cbuf, ho, hseq, t,
            out + OFF_HT, out + OFF_CT);
    }
    // 5) fused layernorm + xh + values/rew
    ln_head_k<<<cBT, 256>>>(hseq, xh, ln_g, ln_b, Wc, Wr, bc, br,
                            out + OFF_VAL, out + OFF_REW);
    // 6+7) combined heads: [logits | obs_pred] = xh @ [Wa;Wobs]^T, N=576
    tgemm_k<64,6><<<dim3((cA+cOBS)/64, cBT/128), 256, SM64>>>(
        xh, whd, out + OFF_LOGITS, out + OFF_OBS, nullptr, ba, bobs, cA+cOBS, cH, 0, 0);
}